// round 14
// baseline (speedup 1.0000x reference)
#include <cuda_runtime.h>
#include <cuda_bf16.h>
#include <cstdint>

// ---------------------------------------------------------------------------
// ArcFace loss on GB300 (sm_103a). FP8 (e4m3) mma.sync GEMM for the LSE sum
// (error-tolerant), exact fp32 recomputation of the single target cosine per
// row in k_final (error-critical). tcgen05 rejected by the harness's
// compute_103 virtual target.
//   k_prep  : rows L2-normalized, scaled x16, quantized to e4m3 (g_wn/g_xn).
//   k_main  : 3128 CTAs (4 M-tiles x 782 chunks of 128 classes), 256 thr,
//             2 CTAs/SM. 3-slot cp.async XW pipeline (128x128B fp8 stages,
//             4 k-chunks), 64x32 warp tiles, ldmatrix.x4 +
//             mma.m16n8k32.e4m3; cos = acc/256; fused exp(64*cos-64) row
//             sums (fixed-max LSE trick).
//   k_final : per-row combine + EXACT fp32 target cos + margin + nll;
//             last block (counter) reduces 512 nll values to the mean.
// ---------------------------------------------------------------------------

namespace {
constexpr int NUM_C = 100000;
constexpr int DIM   = 512;
constexpr int NB    = 512;

constexpr int NPC   = 128;                        // classes per chunk
constexpr int NCCH  = (NUM_C + NPC - 1) / NPC;    // 782
constexpr int NCHP  = 784;                        // padded partial stride
constexpr int CPAD  = NCCH * NPC;                 // 100096

constexpr int SM_X  = 0;                 // 3 stages * 16384 = 49152
constexpr int SM_W  = 49152;             // 3 stages * 16384 = 49152
constexpr size_t SMEM_BYTES = 98304;     // 2 CTAs/SM

constexpr float COS_M = 0.8775825618903728f;   // cos(0.5)
constexpr float SIN_M = 0.479425538604203f;    // sin(0.5)
constexpr float THv   = -0.8775825618903728f;  // -cos(m)
constexpr float MMRG  = 0.2397127693021015f;   // sin(m)*m
} // namespace

__device__ __align__(16) uint8_t g_xn[NB * DIM];              // e4m3, x16
__device__ __align__(16) uint8_t g_wn[(size_t)CPAD * DIM];    // e4m3, x16
__device__ float g_tgt[NB];                                   // fp8-GEMM cos
__device__ float g_partial[(size_t)NB * NCHP];                // [row][chunk]
__device__ float g_nll[NB];
__device__ unsigned g_cnt = 0;

// ---------------------------------------------------------------------------
__device__ __forceinline__ uint32_t smem_u32(const void* p) {
    uint32_t a;
    asm("{ .reg .u64 t; cvta.to.shared.u64 t, %1; cvt.u32.u64 %0, t; }"
        : "=r"(a) : "l"(p));
    return a;
}
#define CP_ASYNC16(dst, src) \
    asm volatile("cp.async.cg.shared.global [%0], [%1], 16;" \
                 :: "r"(dst), "l"(src) : "memory")
#define CP_COMMIT() asm volatile("cp.async.commit_group;" ::: "memory")
#define CP_WAIT1()  asm volatile("cp.async.wait_group 1;" ::: "memory")

#define LDSM4(r, addr) \
    asm volatile("ldmatrix.sync.aligned.m8n8.x4.shared.b16 {%0,%1,%2,%3}, [%4];" \
                 : "=r"((r)[0]), "=r"((r)[1]), "=r"((r)[2]), "=r"((r)[3])        \
                 : "r"(addr))

// fp8 e4m3 MMA: D(16x8,f32) += A(16x32,e4m3) * B(32x8,e4m3)
__device__ __forceinline__ void mma16832(float* c, const uint32_t* a,
                                         const uint32_t* b) {
    asm volatile(
        "mma.sync.aligned.m16n8k32.row.col.f32.e4m3.e4m3.f32 "
        "{%0,%1,%2,%3}, {%4,%5,%6,%7}, {%8,%9}, {%0,%1,%2,%3};\n"
        : "+f"(c[0]), "+f"(c[1]), "+f"(c[2]), "+f"(c[3])
        : "r"(a[0]), "r"(a[1]), "r"(a[2]), "r"(a[3]), "r"(b[0]), "r"(b[1]));
}

// pack 4 floats -> 4 e4m3 bytes (v0 = byte0)
__device__ __forceinline__ uint32_t pack_e4m3(float v0, float v1,
                                              float v2, float v3) {
    uint16_t lo, hi;
    asm("cvt.rn.satfinite.e4m3x2.f32 %0, %1, %2;" : "=h"(lo) : "f"(v1), "f"(v0));
    asm("cvt.rn.satfinite.e4m3x2.f32 %0, %1, %2;" : "=h"(hi) : "f"(v3), "f"(v2));
    return (uint32_t)lo | ((uint32_t)hi << 16);
}

// store one row-slice: v0,v1 = cols 8L..8L+7; v2,v3 = cols 256+8L..+7
__device__ __forceinline__ void norm_store8(float4 v0, float4 v1, float4 v2,
                                            float4 v3, float inv16,
                                            uint8_t* dstrow, int lane) {
    uint2 u0 = { pack_e4m3(v0.x * inv16, v0.y * inv16, v0.z * inv16, v0.w * inv16),
                 pack_e4m3(v1.x * inv16, v1.y * inv16, v1.z * inv16, v1.w * inv16) };
    uint2 u1 = { pack_e4m3(v2.x * inv16, v2.y * inv16, v2.z * inv16, v2.w * inv16),
                 pack_e4m3(v3.x * inv16, v3.y * inv16, v3.z * inv16, v3.w * inv16) };
    *(uint2*)(dstrow + 8 * lane)       = u0;
    *(uint2*)(dstrow + 256 + 8 * lane) = u1;
}

// ---------------------------------------------------------------------------
// Prep: blocks 0..1563 normalize+quantize 64 W rows each (zero past NUM_C);
//       blocks 1564..1565 handle 256 X rows each. Row pairs for MLP.
// ---------------------------------------------------------------------------
__global__ void k_prep(const float* __restrict__ x, const float* __restrict__ w) {
    const int bid  = blockIdx.x;
    const int wid  = threadIdx.x >> 5;
    const int lane = threadIdx.x & 31;

    const bool is_w = (bid < CPAD / 64);
    const float* src_mat = is_w ? w : x;
    const int nrows      = is_w ? NUM_C : NB;
    uint8_t* dst_mat     = is_w ? g_wn : g_xn;
    const int base = is_w ? (bid * 64 + wid * 8)
                          : ((bid - CPAD / 64) * 256 + wid * 32);
    const int per  = is_w ? 8 : 32;

    for (int rp = 0; rp < per; rp += 2) {
        const int r0 = base + rp, r1 = r0 + 1;
        float4 a0, a1, a2, a3, b0, b1, b2, b3;
        const bool ok0 = r0 < nrows, ok1 = r1 < nrows;
        if (ok0) {
            const float4* p = (const float4*)(src_mat + (size_t)r0 * DIM);
            a0 = p[2 * lane]; a1 = p[2 * lane + 1];
            a2 = p[2 * lane + 64]; a3 = p[2 * lane + 65];
        } else a0 = a1 = a2 = a3 = make_float4(0.f, 0.f, 0.f, 0.f);
        if (ok1) {
            const float4* p = (const float4*)(src_mat + (size_t)r1 * DIM);
            b0 = p[2 * lane]; b1 = p[2 * lane + 1];
            b2 = p[2 * lane + 64]; b3 = p[2 * lane + 65];
        } else b0 = b1 = b2 = b3 = make_float4(0.f, 0.f, 0.f, 0.f);

        float s0 = a0.x * a0.x + a0.y * a0.y + a0.z * a0.z + a0.w * a0.w
                 + a1.x * a1.x + a1.y * a1.y + a1.z * a1.z + a1.w * a1.w
                 + a2.x * a2.x + a2.y * a2.y + a2.z * a2.z + a2.w * a2.w
                 + a3.x * a3.x + a3.y * a3.y + a3.z * a3.z + a3.w * a3.w;
        float s1 = b0.x * b0.x + b0.y * b0.y + b0.z * b0.z + b0.w * b0.w
                 + b1.x * b1.x + b1.y * b1.y + b1.z * b1.z + b1.w * b1.w
                 + b2.x * b2.x + b2.y * b2.y + b2.z * b2.z + b2.w * b2.w
                 + b3.x * b3.x + b3.y * b3.y + b3.z * b3.z + b3.w * b3.w;
        #pragma unroll
        for (int o = 16; o; o >>= 1) {
            s0 += __shfl_xor_sync(0xFFFFFFFFu, s0, o);
            s1 += __shfl_xor_sync(0xFFFFFFFFu, s1, o);
        }
        const float i0 = ok0 ? 16.f * rsqrtf(fmaxf(s0, 1e-24f)) : 0.f;
        const float i1 = ok1 ? 16.f * rsqrtf(fmaxf(s1, 1e-24f)) : 0.f;
        norm_store8(a0, a1, a2, a3, i0, dst_mat + (size_t)r0 * DIM, lane);
        if (is_w || ok1)
            norm_store8(b0, b1, b2, b3, i1, dst_mat + (size_t)r1 * DIM, lane);
    }
}

// ---------------------------------------------------------------------------
__global__ void __launch_bounds__(256, 2)
k_main(const int* __restrict__ y) {
    extern __shared__ char smem[];
    const uint32_t sb = smem_u32(smem);
    const int tid  = threadIdx.x;
    const int wid  = tid >> 5;
    const int lane = tid & 31;
    const int mt   = blockIdx.x;           // 0..3 (128-row tile)
    const int cch  = blockIdx.y;           // 0..781
    const int c0   = cch * NPC;
    const int wm   = wid >> 2;             // 0..1  (64-row half)
    const int wn   = wid & 3;              // 0..3  (32-col slice)

    const char* xsrc = (const char*)g_xn + (size_t)mt * 128 * DIM;
    const char* wsrc = (const char*)g_wn + (size_t)c0 * DIM;

    // stage: 128 rows x 128 fp8 bytes = 16KB; 4 k-chunks cover DIM=512.
    #define ISSUE_XW(kc) do {                                                 \
        uint32_t xs_ = sb + SM_X + ((kc) % 3) * 16384;                        \
        uint32_t ws_ = sb + SM_W + ((kc) % 3) * 16384;                        \
        _Pragma("unroll")                                                     \
        for (int i = 0; i < 4; ++i) {                                         \
            int li = tid + 256 * i;                                           \
            int row = li >> 3, seg = li & 7;                                  \
            uint32_t off = row * 128 + ((seg * 16) ^ ((row & 7) << 4));       \
            size_t goff = (size_t)row * DIM + (kc) * 128 + seg * 16;          \
            CP_ASYNC16(xs_ + off, xsrc + goff);                               \
            CP_ASYNC16(ws_ + off, wsrc + goff);                               \
        }                                                                     \
    } while (0)

    ISSUE_XW(0); CP_COMMIT();
    ISSUE_XW(1); CP_COMMIT();

    float acc[4][4][4];
    #pragma unroll
    for (int mi = 0; mi < 4; ++mi)
        #pragma unroll
        for (int ni = 0; ni < 4; ++ni)
            #pragma unroll
            for (int j = 0; j < 4; ++j) acc[mi][ni][j] = 0.f;

    const uint32_t swz      = (lane & 7) << 4;
    const uint32_t xrowbase = (wm * 64 + (lane & 15)) * 128;
    const uint32_t kxA      = (lane >> 4) << 4;
    const uint32_t browbase = (wn * 32 + (lane & 7) + ((lane >> 4) << 3)) * 128;
    const uint32_t kxB      = ((lane >> 3) & 1) << 4;

    for (int kc = 0; kc < 4; ++kc) {
        CP_WAIT1();
        __syncthreads();
        if (kc < 2) ISSUE_XW(kc + 2);
        CP_COMMIT();

        const uint32_t xch = sb + SM_X + (kc % 3) * 16384 + xrowbase;
        const uint32_t wst = sb + SM_W + (kc % 3) * 16384 + browbase;
        #pragma unroll
        for (int ks = 0; ks < 4; ++ks) {
            uint32_t a[4][4], bq[2][4];
            const uint32_t ka = (uint32_t)(ks * 32 + kxA) ^ swz;
            const uint32_t kb = (uint32_t)(ks * 32 + kxB) ^ swz;
            #pragma unroll
            for (int mi = 0; mi < 4; ++mi) LDSM4(a[mi], xch + mi * 2048 + ka);
            #pragma unroll
            for (int nb = 0; nb < 2; ++nb) LDSM4(bq[nb], wst + nb * 2048 + kb);
            #pragma unroll
            for (int mi = 0; mi < 4; ++mi)
                #pragma unroll
                for (int nb = 0; nb < 2; ++nb) {
                    mma16832(acc[mi][2 * nb],     a[mi], &bq[nb][0]);
                    mma16832(acc[mi][2 * nb + 1], a[mi], &bq[nb][2]);
                }
        }
    }

    // ---- epilogue: cos = acc/256 (x16 scales); rowsum exp(64*cos-64) ----
    // racc overlays X stage 1 (last consumed at kc=1; all warps are past the
    // kc>=2 top barriers).
    float* racc = (float*)(smem + SM_X + 16384);
    const int qq = lane & 3;
    const int g8 = lane >> 2;
    const float SC = 1.f / 256.f;

    #pragma unroll
    for (int mi = 0; mi < 4; ++mi) {
        #pragma unroll
        for (int h = 0; h < 2; ++h) {
            const int lrow = wm * 64 + mi * 16 + g8 + 8 * h;
            const int grow = mt * 128 + lrow;
            const int yv   = y[grow];
            float rs = 0.f;
            #pragma unroll
            for (int ni = 0; ni < 4; ++ni) {
                const int cb = c0 + wn * 32 + ni * 8 + 2 * qq;
                float cv0 = acc[mi][ni][2 * h + 0] * SC;
                float cv1 = acc[mi][ni][2 * h + 1] * SC;
                if (cb == yv)     g_tgt[grow] = cv0;
                if (cb + 1 == yv) g_tgt[grow] = cv1;
                float e0 = __expf(fmaf(cv0, 64.f, -64.f));
                float e1 = __expf(fmaf(cv1, 64.f, -64.f));
                if (cb < NUM_C)     rs += e0;
                if (cb + 1 < NUM_C) rs += e1;
            }
            rs += __shfl_xor_sync(0xFFFFFFFFu, rs, 1);
            rs += __shfl_xor_sync(0xFFFFFFFFu, rs, 2);
            if (qq == 0) racc[lrow * 4 + wn] = rs;
        }
    }
    __syncthreads();
    if (tid < 128) {
        float s = racc[tid * 4 + 0] + racc[tid * 4 + 1]
                + racc[tid * 4 + 2] + racc[tid * 4 + 3];
        g_partial[(size_t)(mt * 128 + tid) * NCHP + cch] = s;
    }
    #undef ISSUE_XW
}

// ---------------------------------------------------------------------------
// k_final: block per row. Combines 782 partials, recomputes the target cos
// EXACTLY in fp32, swaps the fp8 target term for the exact margin term,
// then the last block (counter) reduces the 512 nll values to the mean.
__global__ void k_final(const float* __restrict__ x, const float* __restrict__ w,
                        const int* __restrict__ y, float* __restrict__ out) {
    __shared__ float red[8][4];
    __shared__ float sred[256];
    __shared__ int slast;
    const int row = blockIdx.x;
    const int t   = threadIdx.x;
    const int wd  = t >> 5, ln = t & 31;

    float s = 0.f;
    for (int c = t; c < NCCH; c += 256)
        s += g_partial[(size_t)row * NCHP + c];

    // exact target cosine
    const int ycls = y[row];
    float sxw = 0.f, sxx = 0.f, sww = 0.f;
    #pragma unroll
    for (int d = t; d < DIM; d += 256) {
        float xa = x[(size_t)row * DIM + d];
        float wa = w[(size_t)ycls * DIM + d];
        sxw += xa * wa; sxx += xa * xa; sww += wa * wa;
    }
    #pragma unroll
    for (int o = 16; o; o >>= 1) {
        s   += __shfl_xor_sync(0xFFFFFFFFu, s, o);
        sxw += __shfl_xor_sync(0xFFFFFFFFu, sxw, o);
        sxx += __shfl_xor_sync(0xFFFFFFFFu, sxx, o);
        sww += __shfl_xor_sync(0xFFFFFFFFu, sww, o);
    }
    if (ln == 0) { red[wd][0] = s; red[wd][1] = sxw; red[wd][2] = sxx; red[wd][3] = sww; }
    __syncthreads();
    if (t == 0) {
        float S = 0.f, XW = 0.f, XX = 0.f, WW = 0.f;
        #pragma unroll
        for (int k = 0; k < 8; ++k) {
            S += red[k][0]; XW += red[k][1]; XX += red[k][2]; WW += red[k][3];
        }
        float ct  = XW * rsqrtf(fmaxf(XX, 1e-30f)) * rsqrtf(fmaxf(WW, 1e-30f));
        float sn  = sqrtf(fmaxf(1.f - ct * ct, 0.f));
        float cwm = ct * COS_M - sn * SIN_M;
        float phi = (ct > THv) ? cwm : (ct - MMRG);
        // subtract the fp8-GEMM target term, add the exact margin term
        float Sp  = S - __expf(fmaf(g_tgt[row], 64.f, -64.f))
                      + __expf(fmaf(phi, 64.f, -64.f));
        g_nll[row] = 64.f + logf(Sp) - 64.f * phi;
        __threadfence();
        unsigned v = atomicAdd(&g_cnt, 1u);
        slast = (v == (unsigned)(gridDim.x - 1));
    }
    __syncthreads();
    if (slast) {
        __threadfence();
        float v = g_nll[t] + g_nll[t + 256];
        sred[t] = v;
        __syncthreads();
        #pragma unroll
        for (int st = 128; st; st >>= 1) {
            if (t < st) sred[t] += sred[t + st];
            __syncthreads();
        }
        if (t == 0) { out[0] = sred[0] / (float)NB; g_cnt = 0; }
    }
}

// ---------------------------------------------------------------------------
extern "C" void kernel_launch(void* const* d_in, const int* in_sizes, int n_in,
                              void* d_out, int out_size) {
    const float* x = (const float*)d_in[0];
    const int*   y = (const int*)d_in[1];
    const float* w = (const float*)d_in[2];
    float* out = (float*)d_out;

    cudaFuncSetAttribute(k_main, cudaFuncAttributeMaxDynamicSharedMemorySize,
                         (int)SMEM_BYTES);

    k_prep<<<CPAD / 64 + 2, 256>>>(x, w);
    k_main<<<dim3(4, NCCH), 256, SMEM_BYTES>>>(y);
    k_final<<<NB, 256>>>(x, w, y, out);
}